// round 14
// baseline (speedup 1.0000x reference)
#include <cuda_runtime.h>
#include <cuda_fp16.h>
#include <cstdint>
#include <cstddef>

#define TT 2048   // tokens
#define HH 1024   // hidden
#define FF 2048   // ffn
#define EE 8      // experts

// ---------------- static device scratch (allocation-free rule) ----------------
static __device__ __half g_xh[TT * HH];                          // 4 MB
static __device__ __half g_w1h[(size_t)EE * FF * HH];            // 32 MB
static __device__ __half g_v1h[(size_t)EE * FF * HH];            // 32 MB
static __device__ __half g_w2h[(size_t)EE * FF * HH];            // 32 MB
static __device__ __half g_inter[(size_t)EE * TT * FF];          // 64 MB
static __device__ int    g_cnt[EE];
static __device__ int    g_tok[EE * TT];
static __device__ float  g_cw[EE * TT];

// ---------------- small helpers ----------------
__device__ __forceinline__ void cp_async16(void* sdst, const void* gsrc, bool pred) {
    unsigned s = (unsigned)__cvta_generic_to_shared(sdst);
    int sz = pred ? 16 : 0;
    asm volatile("cp.async.cg.shared.global [%0], [%1], 16, %2;\n" :: "r"(s), "l"(gsrc), "r"(sz));
}
__device__ __forceinline__ void cp_commit() { asm volatile("cp.async.commit_group;\n"); }
template <int N>
__device__ __forceinline__ void cp_wait() { asm volatile("cp.async.wait_group %0;\n" :: "n"(N)); }

__device__ __forceinline__ void mma16816(float* c, const uint32_t* a, const uint32_t* b) {
    asm volatile(
        "mma.sync.aligned.m16n8k16.row.col.f32.f16.f16.f32 "
        "{%0,%1,%2,%3}, {%4,%5,%6,%7}, {%8,%9}, {%0,%1,%2,%3};\n"
        : "+f"(c[0]), "+f"(c[1]), "+f"(c[2]), "+f"(c[3])
        : "r"(a[0]), "r"(a[1]), "r"(a[2]), "r"(a[3]), "r"(b[0]), "r"(b[1]));
}
__device__ __forceinline__ void ldsm_x4(uint32_t* r, uint32_t addr) {
    asm volatile("ldmatrix.sync.aligned.m8n8.x4.shared.b16 {%0,%1,%2,%3}, [%4];\n"
                 : "=r"(r[0]), "=r"(r[1]), "=r"(r[2]), "=r"(r[3]) : "r"(addr));
}
__device__ __forceinline__ void ldsm_x4_t(uint32_t* r, uint32_t addr) {
    asm volatile("ldmatrix.sync.aligned.m8n8.x4.trans.shared.b16 {%0,%1,%2,%3}, [%4];\n"
                 : "=r"(r[0]), "=r"(r[1]), "=r"(r[2]), "=r"(r[3]) : "r"(addr));
}

__device__ __forceinline__ uint4 pack8(float4 f0, float4 f1) {
    __half2 h0 = __floats2half2_rn(f0.x, f0.y);
    __half2 h1 = __floats2half2_rn(f0.z, f0.w);
    __half2 h2 = __floats2half2_rn(f1.x, f1.y);
    __half2 h3 = __floats2half2_rn(f1.z, f1.w);
    uint4 u;
    u.x = *(uint32_t*)&h0; u.y = *(uint32_t*)&h1;
    u.z = *(uint32_t*)&h2; u.w = *(uint32_t*)&h3;
    return u;
}

// ---------------- prep kernels ----------------
__global__ void route_kernel(const float* __restrict__ tw, const unsigned int* __restrict__ te) {
    __shared__ unsigned acc;
    const int tid = threadIdx.x;
    if (tid == 0) acc = 0u;
    if (tid < EE) g_cnt[tid] = 0;
    __syncthreads();
    unsigned v = 0;
    for (int j = tid; j < 2048; j += blockDim.x) v |= te[2 * j + 1];
    if (v) atomicOr(&acc, 1u);
    __syncthreads();
    const bool is64 = (acc == 0u);
    const int* te32 = (const int*)te;
    for (int t = tid; t < TT; t += blockDim.x) {
        int e0, e1;
        if (is64) { e0 = te32[4 * t]; e1 = te32[4 * t + 2]; }
        else      { e0 = te32[2 * t]; e1 = te32[2 * t + 1]; }
        float w0 = tw[2 * t], w1 = tw[2 * t + 1];
        if (e0 == e1) {
            int p = atomicAdd(&g_cnt[e0], 1);
            g_tok[e0 * TT + p] = t; g_cw[e0 * TT + p] = w0 + w1;
        } else {
            int p0 = atomicAdd(&g_cnt[e0], 1);
            g_tok[e0 * TT + p0] = t; g_cw[e0 * TT + p0] = w0;
            int p1 = atomicAdd(&g_cnt[e1], 1);
            g_tok[e1 * TT + p1] = t; g_cw[e1 * TT + p1] = w1;
        }
    }
}

// convertA: w1, v1 (2^20 threads each) + x (2^17 threads). 64B per thread.
__global__ void convertA_kernel(const float4* __restrict__ w1, const float4* __restrict__ v1,
                                const float4* __restrict__ x,
                                uint4* __restrict__ d1, uint4* __restrict__ d2,
                                uint4* __restrict__ dx) {
    int i = blockIdx.x * blockDim.x + threadIdx.x;
    int which = i >> 20;
    const float4* s;
    uint4* d;
    int j;
    if (which < 2) {
        s = which ? v1 : w1;
        d = which ? d2 : d1;
        j = (i & ((1 << 20) - 1)) << 2;
    } else {
        s = x; d = dx;
        j = (i - 2 * (1 << 20)) << 2;
        if (j >= (TT * HH / 4)) return;
    }
    float4 f0 = s[j], f1 = s[j + 1], f2 = s[j + 2], f3 = s[j + 3];
    d[(j >> 1)]     = pack8(f0, f1);
    d[(j >> 1) + 1] = pack8(f2, f3);
}

// convertB: w2 only (2^20 threads), 64B per thread.
__global__ void convertB_kernel(const float4* __restrict__ w2, uint4* __restrict__ d3) {
    int i = blockIdx.x * blockDim.x + threadIdx.x;
    int j = i << 2;
    float4 f0 = w2[j], f1 = w2[j + 1], f2 = w2[j + 2], f3 = w2[j + 3];
    d3[(j >> 1)]     = pack8(f0, f1);
    d3[(j >> 1) + 1] = pack8(f2, f3);
}

__global__ void zero_kernel(float4* __restrict__ o, int n4) {
    int i = blockIdx.x * blockDim.x + threadIdx.x;
    if (i < n4) o[i] = make_float4(0.f, 0.f, 0.f, 0.f);
}

// ================= GEMM1: gate/up fused. BM=128, BN=64 (x2 B), BK=64, 3-stage, 2 CTA/SM =======
#define G1_STAGE 18432          // halves per stage: A 128*72 + Bw 64*72 + Bv 64*72
#define G1_BWOFF 9216
#define G1_BVOFF 13824
__global__ __launch_bounds__(256, 2) void gemm1_kernel() {
    const int e  = blockIdx.z;
    const int M  = g_cnt[e];
    const int m0 = blockIdx.y * 128;
    if (m0 >= M) return;
    const int n0 = blockIdx.x * 64;

    extern __shared__ __half sm[];
    const int tid = threadIdx.x;

    int rowA[4]; uint32_t aoff[4]; bool apred[4];
#pragma unroll
    for (int it = 0; it < 4; it++) {
        int q = tid + it * 256;
        rowA[it] = q >> 3;
        int gr = m0 + rowA[it];
        apred[it] = (gr < M);
        aoff[it] = apred[it] ? (uint32_t)g_tok[e * TT + gr] * HH : 0u;
    }
    const int kcA = (tid & 7) * 8;
    int rowB[2];
#pragma unroll
    for (int it = 0; it < 2; it++) rowB[it] = (tid + it * 256) >> 3;
    const int kcB = (tid & 7) * 8;
    size_t boff[2];
#pragma unroll
    for (int it = 0; it < 2; it++) boff[it] = ((size_t)e * FF + n0 + rowB[it]) * HH;

    auto load_stage = [&](int s, int kt) {
        __half* st = sm + s * G1_STAGE;
        int k0 = kt * 64;
#pragma unroll
        for (int it = 0; it < 4; it++)
            cp_async16(st + rowA[it] * 72 + kcA, g_xh + aoff[it] + k0 + kcA, apred[it]);
#pragma unroll
        for (int it = 0; it < 2; it++) {
            cp_async16(st + G1_BWOFF + rowB[it] * 72 + kcB, g_w1h + boff[it] + k0 + kcB, true);
            cp_async16(st + G1_BVOFF + rowB[it] * 72 + kcB, g_v1h + boff[it] + k0 + kcB, true);
        }
    };

    const int wid = tid >> 5, lane = tid & 31;
    const int wm = wid >> 1, wn = wid & 1;
    const int g = lane >> 2, tg = lane & 3;

    const int aOff = (lane & 15) * 72 + (lane >> 4) * 8;
    const int bOff = (((lane >> 4) << 3) + (lane & 7)) * 72 + ((lane >> 3) & 1) * 8;

    const uint32_t sBase = (uint32_t)__cvta_generic_to_shared(sm);

    float cg[2][4][4] = {}, cu[2][4][4] = {};

    const int nk = HH / 64;   // 16
#pragma unroll
    for (int p = 0; p < 3; p++) { load_stage(p, p); cp_commit(); }

    for (int kt = 0; kt < nk; kt++) {
        int s = kt % 3;
        cp_wait<2>();
        __syncthreads();
        const uint32_t stg = sBase + s * (G1_STAGE * 2);
#pragma unroll
        for (int k16 = 0; k16 < 64; k16 += 16) {
            uint32_t a[2][4];
            ldsm_x4(a[0], stg + 2 * ((wm * 32)      * 72 + k16 + aOff));
            ldsm_x4(a[1], stg + 2 * ((wm * 32 + 16) * 72 + k16 + aOff));
            uint32_t bw[4][2], bv[4][2];
#pragma unroll
            for (int p = 0; p < 2; p++) {
                uint32_t r[4];
                ldsm_x4(r, stg + 2 * (G1_BWOFF + (wn * 32 + p * 16) * 72 + k16 + bOff));
                bw[2*p][0] = r[0]; bw[2*p][1] = r[1]; bw[2*p+1][0] = r[2]; bw[2*p+1][1] = r[3];
                ldsm_x4(r, stg + 2 * (G1_BVOFF + (wn * 32 + p * 16) * 72 + k16 + bOff));
                bv[2*p][0] = r[0]; bv[2*p][1] = r[1]; bv[2*p+1][0] = r[2]; bv[2*p+1][1] = r[3];
            }
#pragma unroll
            for (int mi = 0; mi < 2; mi++)
#pragma unroll
                for (int ni = 0; ni < 4; ni++) {
                    mma16816(cg[mi][ni], a[mi], bw[ni]);
                    mma16816(cu[mi][ni], a[mi], bv[ni]);
                }
        }
        __syncthreads();
        if (kt + 3 < nk) load_stage(s, kt + 3);
        cp_commit();
    }

    // epilogue: inter = silu(gate) * up
#pragma unroll
    for (int mi = 0; mi < 2; mi++) {
        int rbase = m0 + wm * 32 + mi * 16 + g;
#pragma unroll
        for (int hlf = 0; hlf < 2; hlf++) {
            int r = rbase + hlf * 8;
            if (r >= M) continue;
            size_t ro = ((size_t)e * TT + r) * FF;
#pragma unroll
            for (int ni = 0; ni < 4; ni++) {
                int c = n0 + wn * 32 + ni * 8 + 2 * tg;
                float g0 = cg[mi][ni][hlf * 2 + 0], g1 = cg[mi][ni][hlf * 2 + 1];
                float u0 = cu[mi][ni][hlf * 2 + 0], u1 = cu[mi][ni][hlf * 2 + 1];
                float h0 = g0 / (1.f + __expf(-g0)) * u0;
                float h1 = g1 / (1.f + __expf(-g1)) * u1;
                *(__half2*)&g_inter[ro + c] = __floats2half2_rn(h0, h1);
            }
        }
    }
}

// ================= GEMM2: down-proj. BM=128, BN=128, BK=32, 4-stage, 2 CTA/SM (R5 exact) =====
#define B2S 136
#define G2_STAGE 9472
#define G2_BOFF 5120
__global__ __launch_bounds__(256, 2) void gemm2_kernel(float* __restrict__ out) {
    const int e  = blockIdx.z;
    const int M  = g_cnt[e];
    const int m0 = blockIdx.y * 128;
    if (m0 >= M) return;
    const int n0 = blockIdx.x * 128;

    extern __shared__ __half sm[];
    const int tid = threadIdx.x;
    int rowA[2];
#pragma unroll
    for (int it = 0; it < 2; it++) rowA[it] = (tid + it * 256) >> 2;
    const int kcA = (tid & 3) * 8;
    const size_t abase = ((size_t)e * TT + m0) * FF;
    const size_t bbase = (size_t)e * FF * HH + n0;

    auto load_stage = [&](int s, int kt) {
        __half* st = sm + s * G2_STAGE;
        int k0 = kt * 32;
#pragma unroll
        for (int it = 0; it < 2; it++)
            cp_async16(st + rowA[it] * 40 + kcA, g_inter + abase + (size_t)rowA[it] * FF + k0 + kcA, true);
#pragma unroll
        for (int it = 0; it < 2; it++) {
            int c = tid + it * 256;
            int kr = c >> 4, nc = (c & 15) * 8;
            cp_async16(st + G2_BOFF + kr * B2S + nc, g_w2h + bbase + (size_t)(k0 + kr) * HH + nc, true);
        }
    };

    const int wid = tid >> 5, lane = tid & 31;
    const int wm = wid >> 1, wn = wid & 1;
    const int g = lane >> 2, tg = lane & 3;

    const int aOff  = (lane & 15) * 40 + (lane >> 4) * 8;
    const int bOffT = ((lane & 7) + ((lane >> 3) & 1) * 8) * B2S + (lane >> 4) * 8;

    const uint32_t sBase = (uint32_t)__cvta_generic_to_shared(sm);

    float c[2][8][4] = {};

    const int nk = FF / 32;
#pragma unroll
    for (int p = 0; p < 3; p++) { load_stage(p, p); cp_commit(); }

    for (int kt = 0; kt < nk; kt++) {
        int s = kt & 3;
        cp_wait<2>();
        __syncthreads();
        const uint32_t stg = sBase + s * (G2_STAGE * 2);
#pragma unroll
        for (int k16 = 0; k16 < 32; k16 += 16) {
            uint32_t a[2][4];
            ldsm_x4(a[0], stg + 2 * ((wm * 32)      * 40 + k16 + aOff));
            ldsm_x4(a[1], stg + 2 * ((wm * 32 + 16) * 40 + k16 + aOff));
            uint32_t b[8][2];
#pragma unroll
            for (int p = 0; p < 4; p++) {
                int ncw = wn * 64 + p * 16;
                uint32_t r[4];
                ldsm_x4_t(r, stg + 2 * (G2_BOFF + k16 * B2S + ncw + bOffT));
                b[2*p][0] = r[0]; b[2*p][1] = r[1]; b[2*p+1][0] = r[2]; b[2*p+1][1] = r[3];
            }
#pragma unroll
            for (int mi = 0; mi < 2; mi++)
#pragma unroll
                for (int ni = 0; ni < 8; ni++)
                    mma16816(c[mi][ni], a[mi], b[ni]);
        }
        int nt = kt + 3;
        if (nt < nk) load_stage(nt & 3, nt);
        cp_commit();
    }

#pragma unroll
    for (int mi = 0; mi < 2; mi++) {
        int rbase = m0 + wm * 32 + mi * 16 + g;
#pragma unroll
        for (int hlf = 0; hlf < 2; hlf++) {
            int r = rbase + hlf * 8;
            if (r >= M) continue;
            int   t = g_tok[e * TT + r];
            float w = g_cw[e * TT + r];
            float* orow = out + (size_t)t * HH;
#pragma unroll
            for (int ni = 0; ni < 8; ni++) {
                int h = n0 + wn * 64 + ni * 8 + 2 * tg;
                atomicAdd(&orow[h],     w * c[mi][ni][hlf * 2 + 0]);
                atomicAdd(&orow[h + 1], w * c[mi][ni][hlf * 2 + 1]);
            }
        }
    }
}

// ---------------- launch ----------------
extern "C" void kernel_launch(void* const* d_in, const int* in_sizes, int n_in,
                              void* d_out, int out_size) {
    const float* x  = (const float*)d_in[0];
    const float* tw = (const float*)d_in[2];
    const void*  te = d_in[3];
    const float* w1 = (const float*)d_in[4];
    const float* v1 = (const float*)d_in[5];
    const float* w2 = (const float*)d_in[6];
    float* out = (float*)d_out;

    void *pxh, *pw1, *pv1, *pw2;
    cudaGetSymbolAddress(&pxh, g_xh);
    cudaGetSymbolAddress(&pw1, g_w1h);
    cudaGetSymbolAddress(&pv1, g_v1h);
    cudaGetSymbolAddress(&pw2, g_w2h);

    const int g1_smem = 3 * G1_STAGE * 2;   // 110592 B
    const int g2_smem = 4 * G2_STAGE * 2;   // 75776 B
    cudaFuncSetAttribute(gemm1_kernel, cudaFuncAttributeMaxDynamicSharedMemorySize, g1_smem);
    cudaFuncSetAttribute(gemm2_kernel, cudaFuncAttributeMaxDynamicSharedMemorySize, g2_smem);

    // Fork a side stream inside the capture: convertB(w2) + zero(out) run
    // concurrently with route/convertA/gemm1 on the main stream; join before gemm2.
    cudaStream_t side;
    cudaStreamCreateWithFlags(&side, cudaStreamNonBlocking);
    cudaEvent_t evFork, evJoin;
    cudaEventCreateWithFlags(&evFork, cudaEventDisableTiming);
    cudaEventCreateWithFlags(&evJoin, cudaEventDisableTiming);

    cudaEventRecord(evFork, 0);
    cudaStreamWaitEvent(side, evFork, 0);

    // side: w2 convert + output zero (only gemm2 depends on these)
    convertB_kernel<<<(1 << 20) / 256, 256, 0, side>>>((const float4*)w2, (uint4*)pw2);
    zero_kernel<<<(out_size / 4 + 255) / 256, 256, 0, side>>>((float4*)d_out, out_size / 4);
    cudaEventRecord(evJoin, side);

    // main: route -> convertA -> gemm1
    route_kernel<<<1, 1024>>>(tw, (const unsigned int*)te);

    const int nA = 2 * (1 << 20) + (1 << 17);
    convertA_kernel<<<nA / 256, 256>>>((const float4*)w1, (const float4*)v1, (const float4*)x,
                                       (uint4*)pw1, (uint4*)pv1, (uint4*)pxh);

    gemm1_kernel<<<dim3(FF / 64, TT / 128, EE), 256, g1_smem>>>();

    cudaStreamWaitEvent(0, evJoin, 0);
    gemm2_kernel<<<dim3(HH / 128, TT / 128, EE), 256, g2_smem>>>(out);
}

// round 16
// speedup vs baseline: 1.0276x; 1.0276x over previous
#include <cuda_runtime.h>
#include <cuda_fp16.h>
#include <cstdint>
#include <cstddef>

#define TT 2048   // tokens
#define HH 1024   // hidden
#define FF 2048   // ffn
#define EE 8      // experts

// ---------------- static device scratch (allocation-free rule) ----------------
static __device__ __half g_xh[TT * HH];                          // 4 MB
static __device__ __half g_w1h[(size_t)EE * FF * HH];            // 32 MB
static __device__ __half g_v1h[(size_t)EE * FF * HH];            // 32 MB
static __device__ __half g_w2h[(size_t)EE * FF * HH];            // 32 MB
static __device__ __half g_inter[(size_t)EE * TT * FF];          // 64 MB
static __device__ int    g_cnt[EE];
static __device__ int    g_tok[EE * TT];
static __device__ float  g_cw[EE * TT];

// ---------------- small helpers ----------------
__device__ __forceinline__ void cp_async16(void* sdst, const void* gsrc, bool pred) {
    unsigned s = (unsigned)__cvta_generic_to_shared(sdst);
    int sz = pred ? 16 : 0;
    asm volatile("cp.async.cg.shared.global [%0], [%1], 16, %2;\n" :: "r"(s), "l"(gsrc), "r"(sz));
}
__device__ __forceinline__ void cp_commit() { asm volatile("cp.async.commit_group;\n"); }
template <int N>
__device__ __forceinline__ void cp_wait() { asm volatile("cp.async.wait_group %0;\n" :: "n"(N)); }

__device__ __forceinline__ void mma16816(float* c, const uint32_t* a, const uint32_t* b) {
    asm volatile(
        "mma.sync.aligned.m16n8k16.row.col.f32.f16.f16.f32 "
        "{%0,%1,%2,%3}, {%4,%5,%6,%7}, {%8,%9}, {%0,%1,%2,%3};\n"
        : "+f"(c[0]), "+f"(c[1]), "+f"(c[2]), "+f"(c[3])
        : "r"(a[0]), "r"(a[1]), "r"(a[2]), "r"(a[3]), "r"(b[0]), "r"(b[1]));
}
__device__ __forceinline__ void ldsm_x4(uint32_t* r, uint32_t addr) {
    asm volatile("ldmatrix.sync.aligned.m8n8.x4.shared.b16 {%0,%1,%2,%3}, [%4];\n"
                 : "=r"(r[0]), "=r"(r[1]), "=r"(r[2]), "=r"(r[3]) : "r"(addr));
}
__device__ __forceinline__ void ldsm_x4_t(uint32_t* r, uint32_t addr) {
    asm volatile("ldmatrix.sync.aligned.m8n8.x4.trans.shared.b16 {%0,%1,%2,%3}, [%4];\n"
                 : "=r"(r[0]), "=r"(r[1]), "=r"(r[2]), "=r"(r[3]) : "r"(addr));
}

__device__ __forceinline__ uint4 pack8(float4 f0, float4 f1) {
    __half2 h0 = __floats2half2_rn(f0.x, f0.y);
    __half2 h1 = __floats2half2_rn(f0.z, f0.w);
    __half2 h2 = __floats2half2_rn(f1.x, f1.y);
    __half2 h3 = __floats2half2_rn(f1.z, f1.w);
    uint4 u;
    u.x = *(uint32_t*)&h0; u.y = *(uint32_t*)&h1;
    u.z = *(uint32_t*)&h2; u.w = *(uint32_t*)&h3;
    return u;
}

// ---------------- prep kernels ----------------
__global__ void route_kernel(const float* __restrict__ tw, const unsigned int* __restrict__ te) {
    __shared__ unsigned acc;
    const int tid = threadIdx.x;
    if (tid == 0) acc = 0u;
    if (tid < EE) g_cnt[tid] = 0;
    __syncthreads();
    unsigned v = 0;
    for (int j = tid; j < 2048; j += blockDim.x) v |= te[2 * j + 1];
    if (v) atomicOr(&acc, 1u);
    __syncthreads();
    const bool is64 = (acc == 0u);
    const int* te32 = (const int*)te;
    for (int t = tid; t < TT; t += blockDim.x) {
        int e0, e1;
        if (is64) { e0 = te32[4 * t]; e1 = te32[4 * t + 2]; }
        else      { e0 = te32[2 * t]; e1 = te32[2 * t + 1]; }
        float w0 = tw[2 * t], w1 = tw[2 * t + 1];
        if (e0 == e1) {
            int p = atomicAdd(&g_cnt[e0], 1);
            g_tok[e0 * TT + p] = t; g_cw[e0 * TT + p] = w0 + w1;
        } else {
            int p0 = atomicAdd(&g_cnt[e0], 1);
            g_tok[e0 * TT + p0] = t; g_cw[e0 * TT + p0] = w0;
            int p1 = atomicAdd(&g_cnt[e1], 1);
            g_tok[e1 * TT + p1] = t; g_cw[e1 * TT + p1] = w1;
        }
    }
}

// convertA: w1, v1 (2^20 threads each) + x (2^17 threads). 64B per thread.
__global__ void convertA_kernel(const float4* __restrict__ w1, const float4* __restrict__ v1,
                                const float4* __restrict__ x,
                                uint4* __restrict__ d1, uint4* __restrict__ d2,
                                uint4* __restrict__ dx) {
    int i = blockIdx.x * blockDim.x + threadIdx.x;
    int which = i >> 20;
    const float4* s;
    uint4* d;
    int j;
    if (which < 2) {
        s = which ? v1 : w1;
        d = which ? d2 : d1;
        j = (i & ((1 << 20) - 1)) << 2;
    } else {
        s = x; d = dx;
        j = (i - 2 * (1 << 20)) << 2;
        if (j >= (TT * HH / 4)) return;
    }
    float4 f0 = s[j], f1 = s[j + 1], f2 = s[j + 2], f3 = s[j + 3];
    d[(j >> 1)]     = pack8(f0, f1);
    d[(j >> 1) + 1] = pack8(f2, f3);
}

// convertB: w2 only (2^20 threads), 64B per thread.
__global__ void convertB_kernel(const float4* __restrict__ w2, uint4* __restrict__ d3) {
    int i = blockIdx.x * blockDim.x + threadIdx.x;
    int j = i << 2;
    float4 f0 = w2[j], f1 = w2[j + 1], f2 = w2[j + 2], f3 = w2[j + 3];
    d3[(j >> 1)]     = pack8(f0, f1);
    d3[(j >> 1) + 1] = pack8(f2, f3);
}

__global__ void zero_kernel(float4* __restrict__ o, int n4) {
    int i = blockIdx.x * blockDim.x + threadIdx.x;
    if (i < n4) o[i] = make_float4(0.f, 0.f, 0.f, 0.f);
}

// ================= GEMM1: gate/up fused. BM=128, BN=64 (x2 B), BK=64, 3-stage, 2 CTA/SM =======
#define G1_STAGE 18432          // halves per stage: A 128*72 + Bw 64*72 + Bv 64*72
#define G1_BWOFF 9216
#define G1_BVOFF 13824
__global__ __launch_bounds__(256, 2) void gemm1_kernel() {
    const int e  = blockIdx.z;
    const int M  = g_cnt[e];
    const int m0 = blockIdx.y * 128;
    if (m0 >= M) return;
    const int n0 = blockIdx.x * 64;

    extern __shared__ __half sm[];
    const int tid = threadIdx.x;

    int rowA[4]; uint32_t aoff[4]; bool apred[4];
#pragma unroll
    for (int it = 0; it < 4; it++) {
        int q = tid + it * 256;
        rowA[it] = q >> 3;
        int gr = m0 + rowA[it];
        apred[it] = (gr < M);
        aoff[it] = apred[it] ? (uint32_t)g_tok[e * TT + gr] * HH : 0u;
    }
    const int kcA = (tid & 7) * 8;
    int rowB[2];
#pragma unroll
    for (int it = 0; it < 2; it++) rowB[it] = (tid + it * 256) >> 3;
    const int kcB = (tid & 7) * 8;
    size_t boff[2];
#pragma unroll
    for (int it = 0; it < 2; it++) boff[it] = ((size_t)e * FF + n0 + rowB[it]) * HH;

    auto load_stage = [&](int s, int kt) {
        __half* st = sm + s * G1_STAGE;
        int k0 = kt * 64;
#pragma unroll
        for (int it = 0; it < 4; it++)
            cp_async16(st + rowA[it] * 72 + kcA, g_xh + aoff[it] + k0 + kcA, apred[it]);
#pragma unroll
        for (int it = 0; it < 2; it++) {
            cp_async16(st + G1_BWOFF + rowB[it] * 72 + kcB, g_w1h + boff[it] + k0 + kcB, true);
            cp_async16(st + G1_BVOFF + rowB[it] * 72 + kcB, g_v1h + boff[it] + k0 + kcB, true);
        }
    };

    const int wid = tid >> 5, lane = tid & 31;
    const int wm = wid >> 1, wn = wid & 1;
    const int g = lane >> 2, tg = lane & 3;

    const int aOff = (lane & 15) * 72 + (lane >> 4) * 8;
    const int bOff = (((lane >> 4) << 3) + (lane & 7)) * 72 + ((lane >> 3) & 1) * 8;

    const uint32_t sBase = (uint32_t)__cvta_generic_to_shared(sm);

    float cg[2][4][4] = {}, cu[2][4][4] = {};

    const int nk = HH / 64;   // 16
#pragma unroll
    for (int p = 0; p < 3; p++) { load_stage(p, p); cp_commit(); }

    for (int kt = 0; kt < nk; kt++) {
        int s = kt % 3;
        cp_wait<2>();
        __syncthreads();
        const uint32_t stg = sBase + s * (G1_STAGE * 2);
#pragma unroll
        for (int k16 = 0; k16 < 64; k16 += 16) {
            uint32_t a[2][4];
            ldsm_x4(a[0], stg + 2 * ((wm * 32)      * 72 + k16 + aOff));
            ldsm_x4(a[1], stg + 2 * ((wm * 32 + 16) * 72 + k16 + aOff));
            uint32_t bw[4][2], bv[4][2];
#pragma unroll
            for (int p = 0; p < 2; p++) {
                uint32_t r[4];
                ldsm_x4(r, stg + 2 * (G1_BWOFF + (wn * 32 + p * 16) * 72 + k16 + bOff));
                bw[2*p][0] = r[0]; bw[2*p][1] = r[1]; bw[2*p+1][0] = r[2]; bw[2*p+1][1] = r[3];
                ldsm_x4(r, stg + 2 * (G1_BVOFF + (wn * 32 + p * 16) * 72 + k16 + bOff));
                bv[2*p][0] = r[0]; bv[2*p][1] = r[1]; bv[2*p+1][0] = r[2]; bv[2*p+1][1] = r[3];
            }
#pragma unroll
            for (int mi = 0; mi < 2; mi++)
#pragma unroll
                for (int ni = 0; ni < 4; ni++) {
                    mma16816(cg[mi][ni], a[mi], bw[ni]);
                    mma16816(cu[mi][ni], a[mi], bv[ni]);
                }
        }
        __syncthreads();
        if (kt + 3 < nk) load_stage(s, kt + 3);
        cp_commit();
    }

    // epilogue: inter = silu(gate) * up
#pragma unroll
    for (int mi = 0; mi < 2; mi++) {
        int rbase = m0 + wm * 32 + mi * 16 + g;
#pragma unroll
        for (int hlf = 0; hlf < 2; hlf++) {
            int r = rbase + hlf * 8;
            if (r >= M) continue;
            size_t ro = ((size_t)e * TT + r) * FF;
#pragma unroll
            for (int ni = 0; ni < 4; ni++) {
                int c = n0 + wn * 32 + ni * 8 + 2 * tg;
                float g0 = cg[mi][ni][hlf * 2 + 0], g1 = cg[mi][ni][hlf * 2 + 1];
                float u0 = cu[mi][ni][hlf * 2 + 0], u1 = cu[mi][ni][hlf * 2 + 1];
                float h0 = g0 / (1.f + __expf(-g0)) * u0;
                float h1 = g1 / (1.f + __expf(-g1)) * u1;
                *(__half2*)&g_inter[ro + c] = __floats2half2_rn(h0, h1);
            }
        }
    }
}

// ================= GEMM2: down-proj. BM=128, BN=128, BK=32, 4-stage, 2 CTA/SM (R5 exact) =====
#define B2S 136
#define G2_STAGE 9472
#define G2_BOFF 5120
__global__ __launch_bounds__(256, 2) void gemm2_kernel(float* __restrict__ out) {
    const int e  = blockIdx.z;
    const int M  = g_cnt[e];
    const int m0 = blockIdx.y * 128;
    if (m0 >= M) return;
    const int n0 = blockIdx.x * 128;

    extern __shared__ __half sm[];
    const int tid = threadIdx.x;
    int rowA[2];
#pragma unroll
    for (int it = 0; it < 2; it++) rowA[it] = (tid + it * 256) >> 2;
    const int kcA = (tid & 3) * 8;
    const size_t abase = ((size_t)e * TT + m0) * FF;
    const size_t bbase = (size_t)e * FF * HH + n0;

    auto load_stage = [&](int s, int kt) {
        __half* st = sm + s * G2_STAGE;
        int k0 = kt * 32;
#pragma unroll
        for (int it = 0; it < 2; it++)
            cp_async16(st + rowA[it] * 40 + kcA, g_inter + abase + (size_t)rowA[it] * FF + k0 + kcA, true);
#pragma unroll
        for (int it = 0; it < 2; it++) {
            int c = tid + it * 256;
            int kr = c >> 4, nc = (c & 15) * 8;
            cp_async16(st + G2_BOFF + kr * B2S + nc, g_w2h + bbase + (size_t)(k0 + kr) * HH + nc, true);
        }
    };

    const int wid = tid >> 5, lane = tid & 31;
    const int wm = wid >> 1, wn = wid & 1;
    const int g = lane >> 2, tg = lane & 3;

    const int aOff  = (lane & 15) * 40 + (lane >> 4) * 8;
    const int bOffT = ((lane & 7) + ((lane >> 3) & 1) * 8) * B2S + (lane >> 4) * 8;

    const uint32_t sBase = (uint32_t)__cvta_generic_to_shared(sm);

    float c[2][8][4] = {};

    const int nk = FF / 32;
#pragma unroll
    for (int p = 0; p < 3; p++) { load_stage(p, p); cp_commit(); }

    for (int kt = 0; kt < nk; kt++) {
        int s = kt & 3;
        cp_wait<2>();
        __syncthreads();
        const uint32_t stg = sBase + s * (G2_STAGE * 2);
#pragma unroll
        for (int k16 = 0; k16 < 32; k16 += 16) {
            uint32_t a[2][4];
            ldsm_x4(a[0], stg + 2 * ((wm * 32)      * 40 + k16 + aOff));
            ldsm_x4(a[1], stg + 2 * ((wm * 32 + 16) * 40 + k16 + aOff));
            uint32_t b[8][2];
#pragma unroll
            for (int p = 0; p < 4; p++) {
                int ncw = wn * 64 + p * 16;
                uint32_t r[4];
                ldsm_x4_t(r, stg + 2 * (G2_BOFF + k16 * B2S + ncw + bOffT));
                b[2*p][0] = r[0]; b[2*p][1] = r[1]; b[2*p+1][0] = r[2]; b[2*p+1][1] = r[3];
            }
#pragma unroll
            for (int mi = 0; mi < 2; mi++)
#pragma unroll
                for (int ni = 0; ni < 8; ni++)
                    mma16816(c[mi][ni], a[mi], b[ni]);
        }
        int nt = kt + 3;
        if (nt < nk) load_stage(nt & 3, nt);
        cp_commit();
    }

#pragma unroll
    for (int mi = 0; mi < 2; mi++) {
        int rbase = m0 + wm * 32 + mi * 16 + g;
#pragma unroll
        for (int hlf = 0; hlf < 2; hlf++) {
            int r = rbase + hlf * 8;
            if (r >= M) continue;
            int   t = g_tok[e * TT + r];
            float w = g_cw[e * TT + r];
            float* orow = out + (size_t)t * HH;
#pragma unroll
            for (int ni = 0; ni < 8; ni++) {
                int h = n0 + wn * 64 + ni * 8 + 2 * tg;
                atomicAdd(&orow[h],     w * c[mi][ni][hlf * 2 + 0]);
                atomicAdd(&orow[h + 1], w * c[mi][ni][hlf * 2 + 1]);
            }
        }
    }
}

// ---------------- launch ----------------
// Streams/events are created ONCE on the first (correctness) call, so they exist
// before the harness takes its pre-capture memory baseline; nothing is allocated
// or freed during capture/replay/teardown. The enqueued GPU work is identical on
// every call.
struct GraphCtx {
    cudaStream_t side1, side2;
    cudaEvent_t  evFork, evA, evRoute, evJoin;
    GraphCtx() {
        cudaStreamCreateWithFlags(&side1, cudaStreamNonBlocking);
        cudaStreamCreateWithFlags(&side2, cudaStreamNonBlocking);
        cudaEventCreateWithFlags(&evFork,  cudaEventDisableTiming);
        cudaEventCreateWithFlags(&evA,     cudaEventDisableTiming);
        cudaEventCreateWithFlags(&evRoute, cudaEventDisableTiming);
        cudaEventCreateWithFlags(&evJoin,  cudaEventDisableTiming);
    }
};

extern "C" void kernel_launch(void* const* d_in, const int* in_sizes, int n_in,
                              void* d_out, int out_size) {
    const float* x  = (const float*)d_in[0];
    const float* tw = (const float*)d_in[2];
    const void*  te = d_in[3];
    const float* w1 = (const float*)d_in[4];
    const float* v1 = (const float*)d_in[5];
    const float* w2 = (const float*)d_in[6];
    float* out = (float*)d_out;

    static GraphCtx ctx;   // created on first call (outside capture)

    void *pxh, *pw1, *pv1, *pw2;
    cudaGetSymbolAddress(&pxh, g_xh);
    cudaGetSymbolAddress(&pw1, g_w1h);
    cudaGetSymbolAddress(&pv1, g_v1h);
    cudaGetSymbolAddress(&pw2, g_w2h);

    const int g1_smem = 3 * G1_STAGE * 2;   // 110592 B
    const int g2_smem = 4 * G2_STAGE * 2;   // 75776 B
    cudaFuncSetAttribute(gemm1_kernel, cudaFuncAttributeMaxDynamicSharedMemorySize, g1_smem);
    cudaFuncSetAttribute(gemm2_kernel, cudaFuncAttributeMaxDynamicSharedMemorySize, g2_smem);

    // fork at entry: route runs on side1 concurrent with convertA
    cudaEventRecord(ctx.evFork, 0);
    cudaStreamWaitEvent(ctx.side1, ctx.evFork, 0);
    route_kernel<<<1, 1024, 0, ctx.side1>>>(tw, (const unsigned int*)te);
    cudaEventRecord(ctx.evRoute, ctx.side1);

    // main: convertA (w1, v1, x) — the only prep on gemm1's critical path
    const int nA = 2 * (1 << 20) + (1 << 17);
    convertA_kernel<<<nA / 256, 256>>>((const float4*)w1, (const float4*)v1, (const float4*)x,
                                       (uint4*)pw1, (uint4*)pv1, (uint4*)pxh);
    cudaEventRecord(ctx.evA, 0);

    // side2: convertB(w2) + zero(out) AFTER convertA completes -> overlaps gemm1 (DRAM-idle)
    cudaStreamWaitEvent(ctx.side2, ctx.evA, 0);
    convertB_kernel<<<(1 << 20) / 256, 256, 0, ctx.side2>>>((const float4*)w2, (uint4*)pw2);
    zero_kernel<<<(out_size / 4 + 255) / 256, 256, 0, ctx.side2>>>((float4*)d_out, out_size / 4);
    cudaEventRecord(ctx.evJoin, ctx.side2);

    // main: gemm1 (needs route + convertA), then gemm2 (needs gemm1 + side2)
    cudaStreamWaitEvent(0, ctx.evRoute, 0);
    gemm1_kernel<<<dim3(FF / 64, TT / 128, EE), 256, g1_smem>>>();

    cudaStreamWaitEvent(0, ctx.evJoin, 0);
    gemm2_kernel<<<dim3(HH / 128, TT / 128, EE), 256, g2_smem>>>(out);
}